// round 11
// baseline (speedup 1.0000x reference)
#include <cuda_runtime.h>
#include <cuda_fp16.h>
#include <cstdint>

// Problem constants
#define D_DIM 768
#define M_DIM 640      // L*B*T
#define V_DIM 30000

// Scratch (no allocation allowed -> __device__ globals)
__device__ float  g_Wt[D_DIM * D_DIM];        // rna(W^T)
__device__ float  g_Ar[M_DIM * D_DIM];        // rna(A)
__device__ __half g_Aph[M_DIM * D_DIM];       // fp16(A @ W)
__device__ __half g_Eh[V_DIM * D_DIM];        // fp16(E)
__device__ float  g_s[M_DIM];                 // A @ b

__device__ __forceinline__ uint32_t f2tf(float f) {
    uint32_t r;
    asm("cvt.rna.tf32.f32 %0, %1;" : "=r"(r) : "f"(f));
    return r;
}
__device__ __forceinline__ void cpasync16(uint32_t saddr, const void* g) {
    asm volatile("cp.async.cg.shared.global [%0], [%1], 16;\n"
                 :: "r"(saddr), "l"(g) : "memory");
}
#define CP_COMMIT() asm volatile("cp.async.commit_group;\n" ::: "memory")
#define CP_WAIT2()  asm volatile("cp.async.wait_group 2;\n" ::: "memory")

__device__ __forceinline__ void ldsm4(uint32_t& r0, uint32_t& r1, uint32_t& r2,
                                      uint32_t& r3, uint32_t addr) {
    asm volatile("ldmatrix.sync.aligned.m8n8.x4.shared.b16 {%0,%1,%2,%3}, [%4];"
                 : "=r"(r0), "=r"(r1), "=r"(r2), "=r"(r3) : "r"(addr));
}

// ---------------------------------------------------------------------------
// Prep kernels
// ---------------------------------------------------------------------------
__global__ void transpose_rna_k(const float* __restrict__ W, float* __restrict__ Wt) {
    __shared__ float t[32][33];
    const int bx = blockIdx.x * 32, by = blockIdx.y * 32;
    const int x = threadIdx.x;
    #pragma unroll
    for (int j = threadIdx.y; j < 32; j += 8)
        t[j][x] = W[(by + j) * D_DIM + bx + x];
    __syncthreads();
    #pragma unroll
    for (int j = threadIdx.y; j < 32; j += 8)
        Wt[(bx + j) * D_DIM + by + x] = __uint_as_float(f2tf(t[x][j]));
}

// Fused: Ar = rna(A) and s = A @ b. One block per row m.
__global__ void roundrow_k(const float* __restrict__ A, const float* __restrict__ b,
                           float* __restrict__ Ar, float* __restrict__ s) {
    __shared__ float red[8];
    const int m = blockIdx.x;
    const int tid = threadIdx.x;
    float acc = 0.f;
    #pragma unroll
    for (int d = tid; d < D_DIM; d += 256) {
        const float a = A[(size_t)m * D_DIM + d];
        Ar[(size_t)m * D_DIM + d] = __uint_as_float(f2tf(a));
        acc += a * b[d];
    }
    #pragma unroll
    for (int o = 16; o; o >>= 1) acc += __shfl_xor_sync(0xffffffffu, acc, o);
    if ((tid & 31) == 0) red[tid >> 5] = acc;
    __syncthreads();
    if (tid < 8) {
        float v = red[tid];
        #pragma unroll
        for (int o = 4; o; o >>= 1) v += __shfl_xor_sync(0xffu, v, o);
        if (tid == 0) s[m] = v;
    }
}

// E (fp32) -> Eh (fp16), grid-stride at limited occupancy (leaves room to co-run
// the gemm1 chain on the other stream).
__global__ void __launch_bounds__(256, 4) convE_k(
    const float* __restrict__ E, __half* __restrict__ Eh, int n8) {
    const int stride = gridDim.x * 256;
    for (int i = blockIdx.x * 256 + threadIdx.x; i < n8; i += stride) {
        const float4* p = reinterpret_cast<const float4*>(E) + (size_t)i * 2;
        float4 x = p[0], y = p[1];
        __half2 h0 = __floats2half2_rn(x.x, x.y);
        __half2 h1 = __floats2half2_rn(x.z, x.w);
        __half2 h2 = __floats2half2_rn(y.x, y.y);
        __half2 h3 = __floats2half2_rn(y.z, y.w);
        uint4 o;
        o.x = *reinterpret_cast<uint32_t*>(&h0);
        o.y = *reinterpret_cast<uint32_t*>(&h1);
        o.z = *reinterpret_cast<uint32_t*>(&h2);
        o.w = *reinterpret_cast<uint32_t*>(&h3);
        reinterpret_cast<uint4*>(Eh)[i] = o;
    }
}

// ---------------------------------------------------------------------------
// GEMM1 (tf32): A'h = fp16(Ar @ Wt^T), 64x64 tiles, m16n8k8, LDS.64 relabel,
// 4-stage cp.async pipeline, single sync per k-tile.
// ---------------------------------------------------------------------------
#define BM1 64
#define BN1 64
#define BK1 32
#define LDS1 40
#define NST1 4
#define STG1F (BM1 * LDS1)

__global__ __launch_bounds__(256, 2) void gemm1_tf32_k(
    const float* __restrict__ A, const float* __restrict__ B, __half* __restrict__ C)
{
    extern __shared__ float smem[];
    float* As = smem;
    float* Bs = smem + NST1 * STG1F;

    const int tid = threadIdx.x;
    const int m0 = blockIdx.x * BM1;
    const int n0 = blockIdx.y * BN1;
    const int KT = D_DIM / BK1;

    const uint32_t sAs = (uint32_t)__cvta_generic_to_shared(As);
    const uint32_t sBs = (uint32_t)__cvta_generic_to_shared(Bs);

    const int lane = tid & 31;
    const int wid  = tid >> 5;
    const int mb = (wid & 3) * 16;
    const int nb = (wid >> 2) * 32;
    const int lr = lane >> 2;
    const int lc = lane & 3;

    float acc[4][4];
    #pragma unroll
    for (int j = 0; j < 4; j++)
        #pragma unroll
        for (int q = 0; q < 4; q++) acc[j][q] = 0.f;

    auto load_tile = [&](int buf, int kt) {
        const int k0 = kt * BK1;
        #pragma unroll
        for (int it = 0; it < 2; it++) {
            const int c  = tid + it * 256;
            const int r  = c >> 3;
            const int kk = (c & 7) << 2;
            cpasync16(sAs + (uint32_t)(buf * STG1F + r * LDS1 + kk) * 4u,
                      A + (size_t)(m0 + r) * D_DIM + k0 + kk);
            cpasync16(sBs + (uint32_t)(buf * STG1F + r * LDS1 + kk) * 4u,
                      B + (size_t)(n0 + r) * D_DIM + k0 + kk);
        }
    };

    #pragma unroll
    for (int p = 0; p < NST1 - 1; p++) { load_tile(p, p); CP_COMMIT(); }

    for (int kt = 0; kt < KT; kt++) {
        CP_WAIT2();
        __syncthreads();

        const int lt = kt + NST1 - 1;
        if (lt < KT) load_tile(lt & 3, lt);
        CP_COMMIT();

        const float* Ab = As + (kt & 3) * STG1F;
        const float* Bb = Bs + (kt & 3) * STG1F;

        #pragma unroll
        for (int ks = 0; ks < 4; ks++) {
            const int kcol = ks * 8 + 2 * lc;
            uint32_t af[4], bf[4][2];
            {
                const int r = mb + lr;
                const float2 v0 = *reinterpret_cast<const float2*>(&Ab[r * LDS1 + kcol]);
                const float2 v1 = *reinterpret_cast<const float2*>(&Ab[(r + 8) * LDS1 + kcol]);
                af[0] = __float_as_uint(v0.x);
                af[1] = __float_as_uint(v1.x);
                af[2] = __float_as_uint(v0.y);
                af[3] = __float_as_uint(v1.y);
            }
            #pragma unroll
            for (int j = 0; j < 4; j++) {
                const int n = nb + j * 8 + lr;
                const float2 v = *reinterpret_cast<const float2*>(&Bb[n * LDS1 + kcol]);
                bf[j][0] = __float_as_uint(v.x);
                bf[j][1] = __float_as_uint(v.y);
            }
            #pragma unroll
            for (int j = 0; j < 4; j++)
                asm volatile(
                    "mma.sync.aligned.m16n8k8.row.col.f32.tf32.tf32.f32 "
                    "{%0,%1,%2,%3}, {%4,%5,%6,%7}, {%8,%9}, {%0,%1,%2,%3};\n"
                    : "+f"(acc[j][0]), "+f"(acc[j][1]), "+f"(acc[j][2]), "+f"(acc[j][3])
                    : "r"(af[0]), "r"(af[1]), "r"(af[2]), "r"(af[3]),
                      "r"(bf[j][0]), "r"(bf[j][1]));
        }
    }

    const int row0 = m0 + mb + lr;
    const int row1 = row0 + 8;
    #pragma unroll
    for (int j = 0; j < 4; j++) {
        const int col = n0 + nb + j * 8 + 2 * lc;
        *reinterpret_cast<__half2*>(C + (size_t)row0 * D_DIM + col) =
            __floats2half2_rn(acc[j][0], acc[j][1]);
        *reinterpret_cast<__half2*>(C + (size_t)row1 * D_DIM + col) =
            __floats2half2_rn(acc[j][2], acc[j][3]);
    }
}

// ---------------------------------------------------------------------------
// GEMM2 (fp16): out = Ah @ Bh^T + bias. 128x256 tiles, BK=64 halves.
// Warp tile 32x128 (acc=128 regs). 4-stage cp.async; XOR swizzle; ldmatrix.x4.
// 1 CTA/SM; single sync per k-tile.
// ---------------------------------------------------------------------------
#define BM2 128
#define BN2 256
#define BK2 64
#define NST 4
#define ASTG 16384                    // 128 rows x 128B
#define BSTG 32768                    // 256 rows x 128B
#define STG  (ASTG + BSTG)            // 49152

__global__ __launch_bounds__(256, 1) void gemm2_fp16_k(
    const __half* __restrict__ A, const __half* __restrict__ B,
    float* __restrict__ C, const float* __restrict__ bias, int N)
{
    extern __shared__ __half smh[];
    const uint32_t sb = (uint32_t)__cvta_generic_to_shared(smh);

    const int tid = threadIdx.x;
    const int m0 = blockIdx.x * BM2;
    const int n0 = blockIdx.y * BN2;
    const int KT = D_DIM / BK2;          // 12

    const int lane = tid & 31;
    const int wid  = tid >> 5;
    const int mb = (wid & 3) * 32;       // 4 warp-rows x 32
    const int nb = (wid >> 2) * 128;     // 2 warp-cols x 128
    const int lr = lane >> 2;
    const int lc = lane & 3;

    const int lrow = lane & 7;
    const int mat  = lane >> 3;
    int aoff[2], arm[2];
    #pragma unroll
    for (int i = 0; i < 2; i++) {
        const int r = mb + i * 16 + ((mat & 1) << 3) + lrow;
        aoff[i] = r * 128;
        arm[i] = r & 7;
    }
    const int acb = mat >> 1;
    int boff[8], brm[8];
    #pragma unroll
    for (int jp = 0; jp < 8; jp++) {
        const int r = nb + (jp * 2 + (mat >> 1)) * 8 + lrow;
        boff[jp] = r * 128;
        brm[jp] = r & 7;
    }
    const int bcb = mat & 1;

    float acc[2][16][4];
    #pragma unroll
    for (int i = 0; i < 2; i++)
        #pragma unroll
        for (int j = 0; j < 16; j++)
            #pragma unroll
            for (int q = 0; q < 4; q++) acc[i][j][q] = 0.f;

    auto load_tile = [&](int buf, int kt) {
        const int k0 = kt * BK2;
        const uint32_t stg = sb + (uint32_t)buf * STG;
        // A: 128 rows x 8 chunks = 1024
        #pragma unroll
        for (int it = 0; it < 4; it++) {
            const int c  = tid + it * 256;
            const int r  = c >> 3;
            const int cc = c & 7;
            const uint32_t soff = (uint32_t)(r * 128 + ((cc ^ (r & 7)) << 4));
            cpasync16(stg + soff, A + (size_t)(m0 + r) * D_DIM + k0 + cc * 8);
        }
        // B: 256 rows x 8 chunks = 2048
        #pragma unroll
        for (int it = 0; it < 8; it++) {
            const int c  = tid + it * 256;
            const int r  = c >> 3;
            const int cc = c & 7;
            const uint32_t soff = (uint32_t)(r * 128 + ((cc ^ (r & 7)) << 4));
            int gr = n0 + r; if (gr >= N) gr = N - 1;
            cpasync16(stg + ASTG + soff, B + (size_t)gr * D_DIM + k0 + cc * 8);
        }
    };

    #pragma unroll
    for (int p = 0; p < NST - 1; p++) { load_tile(p, p); CP_COMMIT(); }

    for (int kt = 0; kt < KT; kt++) {
        CP_WAIT2();
        __syncthreads();

        const int lt = kt + NST - 1;
        if (lt < KT) load_tile(lt & 3, lt);
        CP_COMMIT();

        const uint32_t Ab = sb + (uint32_t)(kt & 3) * STG;
        const uint32_t Bb = Ab + ASTG;

        #pragma unroll
        for (int ks = 0; ks < 4; ks++) {
            uint32_t aq[2][4], bq[8][4];
            #pragma unroll
            for (int i = 0; i < 2; i++)
                ldsm4(aq[i][0], aq[i][1], aq[i][2], aq[i][3],
                      Ab + aoff[i] + (((ks * 2 + acb) ^ arm[i]) << 4));
            #pragma unroll
            for (int jp = 0; jp < 8; jp++)
                ldsm4(bq[jp][0], bq[jp][1], bq[jp][2], bq[jp][3],
                      Bb + boff[jp] + (((ks * 2 + bcb) ^ brm[jp]) << 4));
            #pragma unroll
            for (int i = 0; i < 2; i++)
                #pragma unroll
                for (int j = 0; j < 16; j++) {
                    const uint32_t b0 = bq[j >> 1][(j & 1) * 2];
                    const uint32_t b1 = bq[j >> 1][(j & 1) * 2 + 1];
                    asm volatile(
                        "mma.sync.aligned.m16n8k16.row.col.f32.f16.f16.f32 "
                        "{%0,%1,%2,%3}, {%4,%5,%6,%7}, {%8,%9}, {%0,%1,%2,%3};\n"
                        : "+f"(acc[i][j][0]), "+f"(acc[i][j][1]),
                          "+f"(acc[i][j][2]), "+f"(acc[i][j][3])
                        : "r"(aq[i][0]), "r"(aq[i][1]), "r"(aq[i][2]), "r"(aq[i][3]),
                          "r"(b0), "r"(b1));
                }
        }
    }

    // Epilogue
    #pragma unroll
    for (int i = 0; i < 2; i++) {
        const int row0 = m0 + mb + i * 16 + lr;
        const int row1 = row0 + 8;
        const float sv0 = bias[row0];
        const float sv1 = bias[row1];
        #pragma unroll
        for (int j = 0; j < 16; j++) {
            const int col = n0 + nb + j * 8 + 2 * lc;
            if (col < N) {
                float2 v0 = make_float2(acc[i][j][0] + sv0, acc[i][j][1] + sv0);
                float2 v1 = make_float2(acc[i][j][2] + sv1, acc[i][j][3] + sv1);
                *reinterpret_cast<float2*>(C + (size_t)row0 * N + col) = v0;
                *reinterpret_cast<float2*>(C + (size_t)row1 * N + col) = v1;
            }
        }
    }
}

// ---------------------------------------------------------------------------
// out = (A@W) @ E^T + (A@b)
// Fork-join: convE (limited occupancy) co-runs with {transpose,roundrow,gemm1}.
// ---------------------------------------------------------------------------
extern "C" void kernel_launch(void* const* d_in, const int* in_sizes, int n_in,
                              void* d_out, int out_size) {
    const float* A = (const float*)d_in[0];
    const float* E = (const float*)d_in[1];
    const float* W = (const float*)d_in[2];
    const float* b = (const float*)d_in[3];
    float* out = (float*)d_out;

    float *Wt, *Ar, *s;
    __half *Aph, *Eh;
    cudaGetSymbolAddress((void**)&Wt, g_Wt);
    cudaGetSymbolAddress((void**)&Ar, g_Ar);
    cudaGetSymbolAddress((void**)&s, g_s);
    cudaGetSymbolAddress((void**)&Aph, g_Aph);
    cudaGetSymbolAddress((void**)&Eh, g_Eh);

    const int smem1 = NST1 * 2 * STG1F * 4;    // 81920
    const int smem2 = NST * STG;               // 196608
    cudaFuncSetAttribute(gemm1_tf32_k, cudaFuncAttributeMaxDynamicSharedMemorySize, smem1);
    cudaFuncSetAttribute(gemm2_fp16_k, cudaFuncAttributeMaxDynamicSharedMemorySize, smem2);

    static cudaStream_t s2 = nullptr;
    static cudaEvent_t ef = nullptr, ej = nullptr;
    if (!s2) {
        cudaStreamCreateWithFlags(&s2, cudaStreamNonBlocking);
        cudaEventCreateWithFlags(&ef, cudaEventDisableTiming);
        cudaEventCreateWithFlags(&ej, cudaEventDisableTiming);
    }

    // Fork: convE on side stream at 4 CTAs/SM (leaves warp slots + smem free)
    cudaEventRecord(ef, 0);
    cudaStreamWaitEvent(s2, ef, 0);
    convE_k<<<592, 256, 0, s2>>>(E, Eh, V_DIM * D_DIM / 8);
    cudaEventRecord(ej, s2);

    // Main chain (co-runs with convE)
    transpose_rna_k<<<dim3(24, 24), dim3(32, 8)>>>(W, Wt);
    roundrow_k<<<M_DIM, 256>>>(A, b, Ar, s);
    gemm1_tf32_k<<<dim3(M_DIM / BM1, D_DIM / BN1), 256, smem1>>>(Ar, Wt, Aph);

    // Join, then gemm2
    cudaStreamWaitEvent(0, ej, 0);
    gemm2_fp16_k<<<dim3(M_DIM / BM2, (V_DIM + BN2 - 1) / BN2), 256, smem2>>>(
        Aph, Eh, out, s, V_DIM);
}

// round 17
// speedup vs baseline: 1.1269x; 1.1269x over previous
#include <cuda_runtime.h>
#include <cuda_fp16.h>
#include <cstdint>

// Problem constants
#define D_DIM 768
#define M_DIM 640      // L*B*T
#define V_DIM 30000

// Scratch (no allocation allowed -> __device__ globals)
__device__ float  g_Wt[D_DIM * D_DIM];        // rna(W^T)
__device__ float  g_Ar[M_DIM * D_DIM];        // rna(A)
__device__ __half g_Aph[M_DIM * D_DIM];       // fp16(A @ W)
__device__ __half g_Eh[V_DIM * D_DIM];        // fp16(E)
__device__ float  g_s[M_DIM];                 // A @ b

__device__ __forceinline__ uint32_t f2tf(float f) {
    uint32_t r;
    asm("cvt.rna.tf32.f32 %0, %1;" : "=r"(r) : "f"(f));
    return r;
}
__device__ __forceinline__ void cpasync16(uint32_t saddr, const void* g) {
    asm volatile("cp.async.cg.shared.global [%0], [%1], 16;\n"
                 :: "r"(saddr), "l"(g) : "memory");
}
#define CP_COMMIT() asm volatile("cp.async.commit_group;\n" ::: "memory")
#define CP_WAIT1()  asm volatile("cp.async.wait_group 1;\n" ::: "memory")
#define CP_WAIT2()  asm volatile("cp.async.wait_group 2;\n" ::: "memory")

__device__ __forceinline__ void ldsm4(uint32_t& r0, uint32_t& r1, uint32_t& r2,
                                      uint32_t& r3, uint32_t addr) {
    asm volatile("ldmatrix.sync.aligned.m8n8.x4.shared.b16 {%0,%1,%2,%3}, [%4];"
                 : "=r"(r0), "=r"(r1), "=r"(r2), "=r"(r3) : "r"(addr));
}

// ---------------------------------------------------------------------------
// Fused prep: blocks [0,576) transpose W (24x24 tiles of 32x32), blocks
// [576, 576+640) do roundrow (Ar = rna(A), s = A@b).
// ---------------------------------------------------------------------------
#define PREP_T_BLKS 576   // 24*24

__global__ void prep_k(const float* __restrict__ W, float* __restrict__ Wt,
                       const float* __restrict__ A, const float* __restrict__ b,
                       float* __restrict__ Ar, float* __restrict__ s) {
    const int bx = blockIdx.x;
    const int tid = threadIdx.x;
    if (bx < PREP_T_BLKS) {
        __shared__ float t[32][33];
        const int tbx = (bx % 24) * 32, tby = (bx / 24) * 32;
        const int x = tid & 31, y = tid >> 5;
        #pragma unroll
        for (int j = y; j < 32; j += 8)
            t[j][x] = W[(tby + j) * D_DIM + tbx + x];
        __syncthreads();
        #pragma unroll
        for (int j = y; j < 32; j += 8)
            Wt[(tbx + j) * D_DIM + tby + x] = __uint_as_float(f2tf(t[x][j]));
    } else {
        __shared__ float red[8];
        const int m = bx - PREP_T_BLKS;
        float acc = 0.f;
        #pragma unroll
        for (int d = tid; d < D_DIM; d += 256) {
            const float a = A[(size_t)m * D_DIM + d];
            Ar[(size_t)m * D_DIM + d] = __uint_as_float(f2tf(a));
            acc += a * b[d];
        }
        #pragma unroll
        for (int o = 16; o; o >>= 1) acc += __shfl_xor_sync(0xffffffffu, acc, o);
        if ((tid & 31) == 0) red[tid >> 5] = acc;
        __syncthreads();
        if (tid < 8) {
            float v = red[tid];
            #pragma unroll
            for (int o = 4; o; o >>= 1) v += __shfl_xor_sync(0xffu, v, o);
            if (tid == 0) s[m] = v;
        }
    }
}

// ---------------------------------------------------------------------------
// Fused GEMM1 + convE:
//   blocks [0,120):   A'h = fp16(Ar @ Wt^T), 64x64 tiles, tf32 m16n8k8,
//                     4-stage cp.async, LDS.64 k-slot relabel.
//   blocks [120,296): Eh = fp16(E), grid-stride (structural overlap with gemm1).
// ---------------------------------------------------------------------------
#define BM1 64
#define BN1 64
#define BK1 32
#define LDS1 40
#define NST1 4
#define STG1F (BM1 * LDS1)
#define G1_BLKS 120                  // (640/64) * (768/64)
#define CE_BLKS 176
#define FUSE_BLKS (G1_BLKS + CE_BLKS)

__global__ __launch_bounds__(256, 2) void gemm1_convE_k(
    const float* __restrict__ A, const float* __restrict__ B, __half* __restrict__ C,
    const float* __restrict__ E, __half* __restrict__ Eh, int n8)
{
    const int tid = threadIdx.x;

    if (blockIdx.x >= G1_BLKS) {
        // ----- convE path -----
        const int stride = CE_BLKS * 256;
        for (int i = (blockIdx.x - G1_BLKS) * 256 + tid; i < n8; i += stride) {
            const float4* p = reinterpret_cast<const float4*>(E) + (size_t)i * 2;
            float4 x = p[0], y = p[1];
            __half2 h0 = __floats2half2_rn(x.x, x.y);
            __half2 h1 = __floats2half2_rn(x.z, x.w);
            __half2 h2 = __floats2half2_rn(y.x, y.y);
            __half2 h3 = __floats2half2_rn(y.z, y.w);
            uint4 o;
            o.x = *reinterpret_cast<uint32_t*>(&h0);
            o.y = *reinterpret_cast<uint32_t*>(&h1);
            o.z = *reinterpret_cast<uint32_t*>(&h2);
            o.w = *reinterpret_cast<uint32_t*>(&h3);
            reinterpret_cast<uint4*>(Eh)[i] = o;
        }
        return;
    }

    // ----- gemm1 path -----
    extern __shared__ float smem[];
    float* As = smem;
    float* Bs = smem + NST1 * STG1F;

    const int m0 = (blockIdx.x % 10) * BM1;
    const int n0 = (blockIdx.x / 10) * BN1;
    const int KT = D_DIM / BK1;

    const uint32_t sAs = (uint32_t)__cvta_generic_to_shared(As);
    const uint32_t sBs = (uint32_t)__cvta_generic_to_shared(Bs);

    const int lane = tid & 31;
    const int wid  = tid >> 5;
    const int mb = (wid & 3) * 16;
    const int nb = (wid >> 2) * 32;
    const int lr = lane >> 2;
    const int lc = lane & 3;

    float acc[4][4];
    #pragma unroll
    for (int j = 0; j < 4; j++)
        #pragma unroll
        for (int q = 0; q < 4; q++) acc[j][q] = 0.f;

    auto load_tile = [&](int buf, int kt) {
        const int k0 = kt * BK1;
        #pragma unroll
        for (int it = 0; it < 2; it++) {
            const int c  = tid + it * 256;
            const int r  = c >> 3;
            const int kk = (c & 7) << 2;
            cpasync16(sAs + (uint32_t)(buf * STG1F + r * LDS1 + kk) * 4u,
                      A + (size_t)(m0 + r) * D_DIM + k0 + kk);
            cpasync16(sBs + (uint32_t)(buf * STG1F + r * LDS1 + kk) * 4u,
                      B + (size_t)(n0 + r) * D_DIM + k0 + kk);
        }
    };

    #pragma unroll
    for (int p = 0; p < NST1 - 1; p++) { load_tile(p, p); CP_COMMIT(); }

    for (int kt = 0; kt < KT; kt++) {
        CP_WAIT2();
        __syncthreads();

        const int lt = kt + NST1 - 1;
        if (lt < KT) load_tile(lt & 3, lt);
        CP_COMMIT();

        const float* Ab = As + (kt & 3) * STG1F;
        const float* Bb = Bs + (kt & 3) * STG1F;

        #pragma unroll
        for (int ks = 0; ks < 4; ks++) {
            const int kcol = ks * 8 + 2 * lc;
            uint32_t af[4], bf[4][2];
            {
                const int r = mb + lr;
                const float2 v0 = *reinterpret_cast<const float2*>(&Ab[r * LDS1 + kcol]);
                const float2 v1 = *reinterpret_cast<const float2*>(&Ab[(r + 8) * LDS1 + kcol]);
                af[0] = __float_as_uint(v0.x);
                af[1] = __float_as_uint(v1.x);
                af[2] = __float_as_uint(v0.y);
                af[3] = __float_as_uint(v1.y);
            }
            #pragma unroll
            for (int j = 0; j < 4; j++) {
                const int n = nb + j * 8 + lr;
                const float2 v = *reinterpret_cast<const float2*>(&Bb[n * LDS1 + kcol]);
                bf[j][0] = __float_as_uint(v.x);
                bf[j][1] = __float_as_uint(v.y);
            }
            #pragma unroll
            for (int j = 0; j < 4; j++)
                asm volatile(
                    "mma.sync.aligned.m16n8k8.row.col.f32.tf32.tf32.f32 "
                    "{%0,%1,%2,%3}, {%4,%5,%6,%7}, {%8,%9}, {%0,%1,%2,%3};\n"
                    : "+f"(acc[j][0]), "+f"(acc[j][1]), "+f"(acc[j][2]), "+f"(acc[j][3])
                    : "r"(af[0]), "r"(af[1]), "r"(af[2]), "r"(af[3]),
                      "r"(bf[j][0]), "r"(bf[j][1]));
        }
    }

    const int row0 = m0 + mb + lr;
    const int row1 = row0 + 8;
    #pragma unroll
    for (int j = 0; j < 4; j++) {
        const int col = n0 + nb + j * 8 + 2 * lc;
        *reinterpret_cast<__half2*>(C + (size_t)row0 * D_DIM + col) =
            __floats2half2_rn(acc[j][0], acc[j][1]);
        *reinterpret_cast<__half2*>(C + (size_t)row1 * D_DIM + col) =
            __floats2half2_rn(acc[j][2], acc[j][3]);
    }
}

// ---------------------------------------------------------------------------
// GEMM2 (fp16): out = Ah @ Bh^T + bias. 128x128 tiles, BK=64, 3-stage,
// 2 CTA/SM. Loop order: wait -> SYNC -> LDSM(ks0) -> cp.async+commit -> MMAs.
// (The barrier must precede ALL smem reads of the new stage: wait_group is
//  per-thread; other threads' cp.asyncs are only visible after the barrier.)
// ---------------------------------------------------------------------------
#define BM2 128
#define BN2 128
#define BK2 64
#define NST 3
#define ASTG 16384
#define STG  32768

__global__ __launch_bounds__(256, 2) void gemm2_fp16_k(
    const __half* __restrict__ A, const __half* __restrict__ B,
    float* __restrict__ C, const float* __restrict__ bias, int N)
{
    extern __shared__ __half smh[];
    const uint32_t sb = (uint32_t)__cvta_generic_to_shared(smh);

    const int tid = threadIdx.x;
    const int m0 = blockIdx.x * BM2;
    const int n0 = blockIdx.y * BN2;
    const int KT = D_DIM / BK2;          // 12

    const int lane = tid & 31;
    const int wid  = tid >> 5;
    const int mb = (wid & 3) * 32;
    const int nb = (wid >> 2) * 64;
    const int lr = lane >> 2;
    const int lc = lane & 3;

    const int lrow = lane & 7;
    const int mat  = lane >> 3;
    int aoff[2], arm[2];
    #pragma unroll
    for (int i = 0; i < 2; i++) {
        const int r = mb + i * 16 + ((mat & 1) << 3) + lrow;
        aoff[i] = r * 128;
        arm[i] = r & 7;
    }
    const int acb = mat >> 1;
    int boff[4], brm[4];
    #pragma unroll
    for (int jp = 0; jp < 4; jp++) {
        const int r = nb + (jp * 2 + (mat >> 1)) * 8 + lrow;
        boff[jp] = r * 128;
        brm[jp] = r & 7;
    }
    const int bcb = mat & 1;

    float acc[2][8][4];
    #pragma unroll
    for (int i = 0; i < 2; i++)
        #pragma unroll
        for (int j = 0; j < 8; j++)
            #pragma unroll
            for (int q = 0; q < 4; q++) acc[i][j][q] = 0.f;

    auto load_tile = [&](int buf, int kt) {
        const int k0 = kt * BK2;
        const uint32_t stg = sb + (uint32_t)buf * STG;
        #pragma unroll
        for (int it = 0; it < 4; it++) {
            const int c  = tid + it * 256;
            const int r  = c >> 3;
            const int cc = c & 7;
            const uint32_t soff = (uint32_t)(r * 128 + ((cc ^ (r & 7)) << 4));
            cpasync16(stg + soff, A + (size_t)(m0 + r) * D_DIM + k0 + cc * 8);
            int gr = n0 + r; if (gr >= N) gr = N - 1;
            cpasync16(stg + ASTG + soff, B + (size_t)gr * D_DIM + k0 + cc * 8);
        }
    };

    load_tile(0, 0); CP_COMMIT();
    load_tile(1, 1); CP_COMMIT();

    for (int kt = 0; kt < KT; kt++) {
        CP_WAIT1();                       // my groups for stage kt done
        __syncthreads();                  // everyone's groups visible; also
                                          // separates last iter's reads of
                                          // stage (kt+2)%3 from its overwrite

        const uint32_t Ab = sb + (uint32_t)(kt % NST) * STG;
        const uint32_t Bb = Ab + ASTG;

        // First fragment batch (ks=0), then issue next tile's cp.asyncs so
        // they drain underneath the MMA work.
        uint32_t aq[2][4], bq[4][4];
        #pragma unroll
        for (int i = 0; i < 2; i++)
            ldsm4(aq[i][0], aq[i][1], aq[i][2], aq[i][3],
                  Ab + aoff[i] + ((acb ^ arm[i]) << 4));
        #pragma unroll
        for (int jp = 0; jp < 4; jp++)
            ldsm4(bq[jp][0], bq[jp][1], bq[jp][2], bq[jp][3],
                  Bb + boff[jp] + ((bcb ^ brm[jp]) << 4));

        const int lt = kt + 2;
        if (lt < KT) load_tile(lt % NST, lt);
        CP_COMMIT();

        #pragma unroll
        for (int ks = 0; ks < 4; ks++) {
            if (ks > 0) {
                #pragma unroll
                for (int i = 0; i < 2; i++)
                    ldsm4(aq[i][0], aq[i][1], aq[i][2], aq[i][3],
                          Ab + aoff[i] + (((ks * 2 + acb) ^ arm[i]) << 4));
                #pragma unroll
                for (int jp = 0; jp < 4; jp++)
                    ldsm4(bq[jp][0], bq[jp][1], bq[jp][2], bq[jp][3],
                          Bb + boff[jp] + (((ks * 2 + bcb) ^ brm[jp]) << 4));
            }
            #pragma unroll
            for (int i = 0; i < 2; i++)
                #pragma unroll
                for (int j = 0; j < 8; j++) {
                    const uint32_t b0 = bq[j >> 1][(j & 1) * 2];
                    const uint32_t b1 = bq[j >> 1][(j & 1) * 2 + 1];
                    asm volatile(
                        "mma.sync.aligned.m16n8k16.row.col.f32.f16.f16.f32 "
                        "{%0,%1,%2,%3}, {%4,%5,%6,%7}, {%8,%9}, {%0,%1,%2,%3};\n"
                        : "+f"(acc[i][j][0]), "+f"(acc[i][j][1]),
                          "+f"(acc[i][j][2]), "+f"(acc[i][j][3])
                        : "r"(aq[i][0]), "r"(aq[i][1]), "r"(aq[i][2]), "r"(aq[i][3]),
                          "r"(b0), "r"(b1));
                }
        }
    }

    #pragma unroll
    for (int i = 0; i < 2; i++) {
        const int row0 = m0 + mb + i * 16 + lr;
        const int row1 = row0 + 8;
        const float sv0 = bias[row0];
        const float sv1 = bias[row1];
        #pragma unroll
        for (int j = 0; j < 8; j++) {
            const int col = n0 + nb + j * 8 + 2 * lc;
            if (col < N) {
                float2 v0 = make_float2(acc[i][j][0] + sv0, acc[i][j][1] + sv0);
                float2 v1 = make_float2(acc[i][j][2] + sv1, acc[i][j][3] + sv1);
                *reinterpret_cast<float2*>(C + (size_t)row0 * N + col) = v0;
                *reinterpret_cast<float2*>(C + (size_t)row1 * N + col) = v1;
            }
        }
    }
}

// ---------------------------------------------------------------------------
// out = (A@W) @ E^T + (A@b)
// ---------------------------------------------------------------------------
extern "C" void kernel_launch(void* const* d_in, const int* in_sizes, int n_in,
                              void* d_out, int out_size) {
    const float* A = (const float*)d_in[0];
    const float* E = (const float*)d_in[1];
    const float* W = (const float*)d_in[2];
    const float* b = (const float*)d_in[3];
    float* out = (float*)d_out;

    float *Wt, *Ar, *s;
    __half *Aph, *Eh;
    cudaGetSymbolAddress((void**)&Wt, g_Wt);
    cudaGetSymbolAddress((void**)&Ar, g_Ar);
    cudaGetSymbolAddress((void**)&s, g_s);
    cudaGetSymbolAddress((void**)&Aph, g_Aph);
    cudaGetSymbolAddress((void**)&Eh, g_Eh);

    const int smem1 = NST1 * 2 * STG1F * 4;    // 81920
    const int smem2 = NST * STG;               // 98304
    cudaFuncSetAttribute(gemm1_convE_k, cudaFuncAttributeMaxDynamicSharedMemorySize, smem1);
    cudaFuncSetAttribute(gemm2_fp16_k, cudaFuncAttributeMaxDynamicSharedMemorySize, smem2);

    // 1) prep: Wt = rna(W^T), Ar = rna(A), s = A@b
    prep_k<<<PREP_T_BLKS + M_DIM, 256>>>(W, Wt, A, b, Ar, s);
    // 2) fused: A'h = fp16(A@W)  ||  Eh = fp16(E)   (structural overlap)
    gemm1_convE_k<<<FUSE_BLKS, 256, smem1>>>(Ar, Wt, Aph, E, Eh, V_DIM * D_DIM / 8);
    // 3) out = A'h @ Eh^T + s
    gemm2_fp16_k<<<dim3(M_DIM / BM2, (V_DIM + BN2 - 1) / BN2), 256, smem2>>>(
        Aph, Eh, out, s, V_DIM);
}